// round 15
// baseline (speedup 1.0000x reference)
#include <cuda_runtime.h>
#include <cuda_fp16.h>

// ---------------- problem constants ----------------
#define NN 100000
#define EE 1600000
#define CAP 64               // bucket capacity per node (max in-degree+1 ~ 43)
#define L2E 1.4426950408889634f
#define HALF_N 50048         // agg1/gemm2 split point (mult of 128 and 8)
#define DUMMY1 ((unsigned)NN * 288u)

// ---------------- device scratch (no allocs allowed) ----------------
__device__ int    g_is64;
__device__ int    g_deg[NN];
__device__ unsigned g_csrb[NN * CAP];    // adjacency: BYTE offsets src*288
// layer-1 node record: 288B = 8 x f32 prescaled-as1 | 128 x f16 h1  (+1 dummy)
__device__ uint4  g_n1[(NN + 1) * 18];
__device__ float  g_ad1[NN * 8];         // prescaled by log2e
__device__ __half g_x2h[NN * 128];       // layer-2 input, fp16
// layer-2 node record: 72B = f32 prescaled-as2 | 32 x f16 h2 | 4B pad (+1 dummy)
__device__ unsigned long long g_n2[(NN + 1) * 9];
__device__ float  g_ad2[NN];             // prescaled by log2e

// ---------------- helpers ----------------
__device__ __forceinline__ float eluf(float x)  { return x > 0.f ? x : __expf(x) - 1.f; }
__device__ __forceinline__ float ex2f(float y) {
    float w;
    asm("ex2.approx.ftz.f32 %0, %1;" : "=f"(w) : "f"(y));
    return w;
}
// exp(lrelu(x/l2e)) where x is prescaled: ex2(max(x, 0.2x))
__device__ __forceinline__ float wexp(float x) {
    return ex2f(fmaxf(x, 0.2f * x));
}

// ---------------- init: seed buckets + dummy record + dtype detection -------
__global__ void k_init(const int* __restrict__ ei) {
    int i = blockIdx.x * blockDim.x + threadIdx.x;
    if (i < NN) {
        g_deg[i] = 1;                     // slot 0 = self loop
        g_csrb[i * CAP] = (unsigned)i * 288u;
    }
    if (blockIdx.x == 0) {
        int t = threadIdx.x;
        if (t < 32) {
            int z = 0;
#pragma unroll
            for (int j = 0; j < 4; j++) z |= ei[2 * (t * 4 + j) + 1];
#pragma unroll
            for (int o = 16; o > 0; o >>= 1) z |= __shfl_xor_sync(0xffffffffu, z, o);
            if (t == 0) g_is64 = (z == 0) ? 1 : 0;
        }
        // dummy node record NN: logits = -1e30 (w = 0), features = 0
        if (t >= 32 && t < 50) {
            int q = t - 32;               // 0..17 -> n1 dummy uint4s
            uint4 v = make_uint4(0, 0, 0, 0);
            if (q < 2) {
                unsigned u = __float_as_uint(-1e30f);
                v = make_uint4(u, u, u, u);
            }
            g_n1[NN * 18 + q] = v;
        }
        if (t >= 50 && t < 59) {
            int q = t - 50;               // 0..8 -> n2 dummy u64s
            g_n2[NN * 9 + q] = (q == 0)
                ? (unsigned long long)__float_as_uint(-1e30f) : 0ull;
        }
    }
}

// ---------------- single-pass bucket fill ----------------
__global__ void k_fill(const int* __restrict__ ei) {
    int e = blockIdx.x * blockDim.x + threadIdx.x;
    if (e >= EE) return;
    int s, d;
    if (g_is64) {
        s = ((const int2*)ei)[e].x;
        d = ((const int2*)ei)[EE + e].x;
    } else {
        s = ei[e];
        d = ei[EE + e];
    }
    int pos = atomicAdd(&g_deg[d], 1);
    g_csrb[d * CAP + pos] = (unsigned)s * 288u;
}

// ---------------- GEMM1 via HMMA: h1 = x @ W1 [128x128] fp16 in, fp32 acc ---
#define APITCH 72    // halfs; 144B rows
#define BPITCH 136   // halfs; 272B rows

__device__ __forceinline__ uint4 pack8(float4 v0, float4 v1) {
    __half2 h0 = __floats2half2_rn(v0.x, v0.y);
    __half2 h1 = __floats2half2_rn(v0.z, v0.w);
    __half2 h2 = __floats2half2_rn(v1.x, v1.y);
    __half2 h3 = __floats2half2_rn(v1.z, v1.w);
    uint4 u;
    u.x = *(unsigned*)&h0; u.y = *(unsigned*)&h1;
    u.z = *(unsigned*)&h2; u.w = *(unsigned*)&h3;
    return u;
}

__global__ void __launch_bounds__(256, 2)
k_gemm1(const float* __restrict__ x, const float* __restrict__ W,
        const float* __restrict__ asv, const float* __restrict__ adv) {
    __shared__ __half As[128 * APITCH];
    __shared__ __half Bs[64 * BPITCH];
    int t = threadIdx.x;
    int lane = t & 31, wid = t >> 5;
    int warp_m = wid >> 1, warp_n = wid & 1;
    int row0 = blockIdx.x * 128;

    float acc[2][8][4];
#pragma unroll
    for (int mt = 0; mt < 2; mt++)
#pragma unroll
        for (int nt = 0; nt < 8; nt++)
#pragma unroll
            for (int q = 0; q < 4; q++) acc[mt][nt][q] = 0.f;

    for (int kc = 0; kc < 2; kc++) {
        __syncthreads();
#pragma unroll
        for (int it = 0; it < 4; it++) {
            int idx = it * 256 + t;
            int r = idx >> 3, c8 = (idx & 7) << 3;
            float4 v0 = make_float4(0.f, 0.f, 0.f, 0.f), v1 = v0;
            if (row0 + r < NN) {
                const float* p = x + (size_t)(row0 + r) * 128 + kc * 64 + c8;
                v0 = *(const float4*)p;
                v1 = *(const float4*)(p + 4);
            }
            *(uint4*)(As + r * APITCH + c8) = pack8(v0, v1);
        }
#pragma unroll
        for (int it = 0; it < 4; it++) {
            int idx = it * 256 + t;
            int k = idx >> 4, nc = (idx & 15) << 3;
            const float* p = W + (size_t)(kc * 64 + k) * 128 + nc;
            float4 v0 = *(const float4*)p;
            float4 v1 = *(const float4*)(p + 4);
            *(uint4*)(Bs + k * BPITCH + nc) = pack8(v0, v1);
        }
        __syncthreads();

#pragma unroll
        for (int ks = 0; ks < 4; ks++) {
            unsigned af[2][4], bf[4][4];
#pragma unroll
            for (int mt = 0; mt < 2; mt++) {
                int r = warp_m * 32 + mt * 16 + (lane & 15);
                int k = ks * 16 + ((lane >> 4) << 3);
                unsigned ad = (unsigned)__cvta_generic_to_shared(As + r * APITCH + k);
                asm volatile("ldmatrix.sync.aligned.m8n8.x4.shared.b16 {%0,%1,%2,%3}, [%4];"
                             : "=r"(af[mt][0]), "=r"(af[mt][1]), "=r"(af[mt][2]), "=r"(af[mt][3])
                             : "r"(ad));
            }
#pragma unroll
            for (int np = 0; np < 4; np++) {
                int k = ks * 16 + (lane & 15);
                int n = warp_n * 64 + np * 16 + ((lane >> 4) << 3);
                unsigned ad = (unsigned)__cvta_generic_to_shared(Bs + k * BPITCH + n);
                asm volatile("ldmatrix.sync.aligned.m8n8.x4.trans.shared.b16 {%0,%1,%2,%3}, [%4];"
                             : "=r"(bf[np][0]), "=r"(bf[np][1]), "=r"(bf[np][2]), "=r"(bf[np][3])
                             : "r"(ad));
            }
#pragma unroll
            for (int mt = 0; mt < 2; mt++)
#pragma unroll
                for (int nt = 0; nt < 8; nt++) {
                    unsigned b0 = bf[nt >> 1][(nt & 1) * 2];
                    unsigned b1 = bf[nt >> 1][(nt & 1) * 2 + 1];
                    asm volatile(
                        "mma.sync.aligned.m16n8k16.row.col.f32.f16.f16.f32 "
                        "{%0,%1,%2,%3}, {%4,%5,%6,%7}, {%8,%9}, {%0,%1,%2,%3};"
                        : "+f"(acc[mt][nt][0]), "+f"(acc[mt][nt][1]),
                          "+f"(acc[mt][nt][2]), "+f"(acc[mt][nt][3])
                        : "r"(af[mt][0]), "r"(af[mt][1]), "r"(af[mt][2]), "r"(af[mt][3]),
                          "r"(b0), "r"(b1));
                }
        }
    }

    float aw0[8], aw1[8], dw0[8], dw1[8];
#pragma unroll
    for (int nt = 0; nt < 8; nt++) {
        int col = warp_n * 64 + nt * 8 + (lane & 3) * 2;
        aw0[nt] = asv[col];     aw1[nt] = asv[col + 1];
        dw0[nt] = adv[col];     dw1[nt] = adv[col + 1];
    }
    char* n1b = (char*)g_n1;
#pragma unroll
    for (int mt = 0; mt < 2; mt++) {
        int row_lo = row0 + warp_m * 32 + mt * 16 + (lane >> 2);
        int row_hi = row_lo + 8;
        float slo[4] = {0,0,0,0}, shi[4] = {0,0,0,0};
        float dlo[4] = {0,0,0,0}, dhi[4] = {0,0,0,0};
#pragma unroll
        for (int nt = 0; nt < 8; nt++) {
            float c0 = acc[mt][nt][0], c1 = acc[mt][nt][1];
            float c2 = acc[mt][nt][2], c3 = acc[mt][nt][3];
            int col = warp_n * 64 + nt * 8 + (lane & 3) * 2;
            if (row_lo < NN) {
                __half2 h = __floats2half2_rn(c0, c1);
                *(__half2*)(n1b + (size_t)row_lo * 288 + 32 + col * 2) = h;
            }
            if (row_hi < NN) {
                __half2 h = __floats2half2_rn(c2, c3);
                *(__half2*)(n1b + (size_t)row_hi * 288 + 32 + col * 2) = h;
            }
            int hl = nt >> 1;
            slo[hl] = fmaf(c0, aw0[nt], fmaf(c1, aw1[nt], slo[hl]));
            shi[hl] = fmaf(c2, aw0[nt], fmaf(c3, aw1[nt], shi[hl]));
            dlo[hl] = fmaf(c0, dw0[nt], fmaf(c1, dw1[nt], dlo[hl]));
            dhi[hl] = fmaf(c2, dw0[nt], fmaf(c3, dw1[nt], dhi[hl]));
        }
#pragma unroll
        for (int hl = 0; hl < 4; hl++) {
            slo[hl] += __shfl_xor_sync(0xffffffffu, slo[hl], 1);
            slo[hl] += __shfl_xor_sync(0xffffffffu, slo[hl], 2);
            shi[hl] += __shfl_xor_sync(0xffffffffu, shi[hl], 1);
            shi[hl] += __shfl_xor_sync(0xffffffffu, shi[hl], 2);
            dlo[hl] += __shfl_xor_sync(0xffffffffu, dlo[hl], 1);
            dlo[hl] += __shfl_xor_sync(0xffffffffu, dlo[hl], 2);
            dhi[hl] += __shfl_xor_sync(0xffffffffu, dhi[hl], 1);
            dhi[hl] += __shfl_xor_sync(0xffffffffu, dhi[hl], 2);
        }
        if ((lane & 3) == 0) {
            int hbase = warp_n * 4;
#pragma unroll
            for (int hl = 0; hl < 4; hl++) {
                int h = hbase + hl;
                if (row_lo < NN) {
                    *(float*)(n1b + (size_t)row_lo * 288 + h * 4) = slo[hl] * L2E;
                    g_ad1[row_lo * 8 + h] = dlo[hl] * L2E;
                }
                if (row_hi < NN) {
                    *(float*)(n1b + (size_t)row_hi * 288 + h * 4) = shi[hl] * L2E;
                    g_ad1[row_hi * 8 + h] = dhi[hl] * L2E;
                }
            }
        }
    }
}

// ---------------- Layer-1 fused attention + aggregation ----------------
// Warp per node; lane owns 4 channels (head = lane/4). Full batches of 8/4
// over real edges; final partial batch predicated with the dummy (w=0)
// record offset — no separate pad kernel, no scalar tail.
__global__ void k_agg1(const float* __restrict__ b1, int n0) {
    int wid = threadIdx.x >> 5, lane = threadIdx.x & 31;
    int n = n0 + blockIdx.x * 8 + wid;
    if (n >= NN) return;
    int beg = n * CAP;
    int deg = g_deg[n];
    int end4 = beg + (deg & ~3);
    int rem = deg & 3;
    int offA = (lane >> 2) * 4;
    int offH = 32 + lane * 8;
    const char* n1b = (const char*)g_n1;

    float ad = g_ad1[n * 8 + (lane >> 2)];   // prescaled by log2e

    float4 acc = make_float4(0.f, 0.f, 0.f, 0.f);
    float s = 0.f;
    int i = beg;
    for (; i + 8 <= end4; i += 8) {
        unsigned o[8];
#pragma unroll
        for (int j = 0; j < 8; j++) o[j] = __ldg(g_csrb + i + j);
        float av[8];
#pragma unroll
        for (int j = 0; j < 8; j++) av[j] = __ldg((const float*)(n1b + o[j] + offA));
        uint2 uv[8];
#pragma unroll
        for (int j = 0; j < 8; j++) uv[j] = __ldg((const uint2*)(n1b + o[j] + offH));
#pragma unroll
        for (int j = 0; j < 8; j++) {
            float w = wexp(av[j] + ad);
            s += w;
            float2 f0 = __half22float2(*(__half2*)&uv[j].x);
            float2 f1 = __half22float2(*(__half2*)&uv[j].y);
            acc.x = fmaf(w, f0.x, acc.x); acc.y = fmaf(w, f0.y, acc.y);
            acc.z = fmaf(w, f1.x, acc.z); acc.w = fmaf(w, f1.y, acc.w);
        }
    }
    if (i < end4) {
        unsigned o[4];
#pragma unroll
        for (int j = 0; j < 4; j++) o[j] = __ldg(g_csrb + i + j);
        float av[4];
#pragma unroll
        for (int j = 0; j < 4; j++) av[j] = __ldg((const float*)(n1b + o[j] + offA));
        uint2 uv[4];
#pragma unroll
        for (int j = 0; j < 4; j++) uv[j] = __ldg((const uint2*)(n1b + o[j] + offH));
#pragma unroll
        for (int j = 0; j < 4; j++) {
            float w = wexp(av[j] + ad);
            s += w;
            float2 f0 = __half22float2(*(__half2*)&uv[j].x);
            float2 f1 = __half22float2(*(__half2*)&uv[j].y);
            acc.x = fmaf(w, f0.x, acc.x); acc.y = fmaf(w, f0.y, acc.y);
            acc.z = fmaf(w, f1.x, acc.z); acc.w = fmaf(w, f1.y, acc.w);
        }
        i += 4;
    }
    if (rem) {   // predicated final batch: missing slots use dummy (w = 0)
        unsigned o[4];
#pragma unroll
        for (int j = 0; j < 4; j++) o[j] = (j < rem) ? __ldg(g_csrb + i + j) : DUMMY1;
        float av[4];
#pragma unroll
        for (int j = 0; j < 4; j++) av[j] = __ldg((const float*)(n1b + o[j] + offA));
        uint2 uv[4];
#pragma unroll
        for (int j = 0; j < 4; j++) uv[j] = __ldg((const uint2*)(n1b + o[j] + offH));
#pragma unroll
        for (int j = 0; j < 4; j++) {
            float w = wexp(av[j] + ad);
            s += w;
            float2 f0 = __half22float2(*(__half2*)&uv[j].x);
            float2 f1 = __half22float2(*(__half2*)&uv[j].y);
            acc.x = fmaf(w, f0.x, acc.x); acc.y = fmaf(w, f0.y, acc.y);
            acc.z = fmaf(w, f1.x, acc.z); acc.w = fmaf(w, f1.y, acc.w);
        }
    }
    float rv = 1.f / s;   // s >= w(selfloop) > 0
    float4 bb = *(const float4*)(b1 + lane * 4);
    __half2 o0 = __floats2half2_rn(eluf(fmaf(acc.x, rv, bb.x)), eluf(fmaf(acc.y, rv, bb.y)));
    __half2 o1 = __floats2half2_rn(eluf(fmaf(acc.z, rv, bb.z)), eluf(fmaf(acc.w, rv, bb.w)));
    uint2 ov;
    ov.x = *(unsigned*)&o0;
    ov.y = *(unsigned*)&o1;
    *(uint2*)(g_x2h + (size_t)n * 128 + lane * 4) = ov;
}

// ---------------- GEMM2 via HMMA: h2 = x2h @ W2 [128x32] fp16 in, fp32 acc --
#define A2PITCH 136   // halfs; 272B rows
#define B2PITCH 40    // halfs; 80B rows
__global__ void __launch_bounds__(256, 2)
k_gemm2(const float* __restrict__ W, const float* __restrict__ a2s,
        const float* __restrict__ a2d, int r0) {
    __shared__ __half As[128 * A2PITCH];
    __shared__ __half Bs[128 * B2PITCH];
    int t = threadIdx.x;
    int lane = t & 31, wid = t >> 5;
    int row0 = r0 + blockIdx.x * 128;

#pragma unroll
    for (int it = 0; it < 8; it++) {
        int idx = it * 256 + t;
        int r = idx >> 4, c = (idx & 15) << 3;
        uint4 v = make_uint4(0, 0, 0, 0);
        if (row0 + r < NN) v = *(const uint4*)(g_x2h + (size_t)(row0 + r) * 128 + c);
        *(uint4*)(As + r * A2PITCH + c) = v;
    }
#pragma unroll
    for (int it = 0; it < 8; it++) {
        int idx = it * 256 + t;
        int k = idx >> 4, n2 = (idx & 15) << 1;
        float2 w = *(const float2*)(W + k * 32 + n2);
        *(__half2*)(Bs + k * B2PITCH + n2) = __floats2half2_rn(w.x, w.y);
    }
    __syncthreads();

    float acc[4][4];
#pragma unroll
    for (int nt = 0; nt < 4; nt++)
#pragma unroll
        for (int q = 0; q < 4; q++) acc[nt][q] = 0.f;

#pragma unroll
    for (int ks = 0; ks < 8; ks++) {
        unsigned af[4], bf[2][4];
        {
            int r = wid * 16 + (lane & 15);
            int k = ks * 16 + ((lane >> 4) << 3);
            unsigned ad = (unsigned)__cvta_generic_to_shared(As + r * A2PITCH + k);
            asm volatile("ldmatrix.sync.aligned.m8n8.x4.shared.b16 {%0,%1,%2,%3}, [%4];"
                         : "=r"(af[0]), "=r"(af[1]), "=r"(af[2]), "=r"(af[3]) : "r"(ad));
        }
#pragma unroll
        for (int np = 0; np < 2; np++) {
            int k = ks * 16 + (lane & 15);
            int n = np * 16 + ((lane >> 4) << 3);
            unsigned ad = (unsigned)__cvta_generic_to_shared(Bs + k * B2PITCH + n);
            asm volatile("ldmatrix.sync.aligned.m8n8.x4.trans.shared.b16 {%0,%1,%2,%3}, [%4];"
                         : "=r"(bf[np][0]), "=r"(bf[np][1]), "=r"(bf[np][2]), "=r"(bf[np][3])
                         : "r"(ad));
        }
#pragma unroll
        for (int nt = 0; nt < 4; nt++) {
            unsigned b0 = bf[nt >> 1][(nt & 1) * 2];
            unsigned b1 = bf[nt >> 1][(nt & 1) * 2 + 1];
            asm volatile(
                "mma.sync.aligned.m16n8k16.row.col.f32.f16.f16.f32 "
                "{%0,%1,%2,%3}, {%4,%5,%6,%7}, {%8,%9}, {%0,%1,%2,%3};"
                : "+f"(acc[nt][0]), "+f"(acc[nt][1]), "+f"(acc[nt][2]), "+f"(acc[nt][3])
                : "r"(af[0]), "r"(af[1]), "r"(af[2]), "r"(af[3]), "r"(b0), "r"(b1));
        }
    }

    char* n2b = (char*)g_n2;
    int row_lo = row0 + wid * 16 + (lane >> 2);
    int row_hi = row_lo + 8;
    float slo = 0.f, shi = 0.f, dlo = 0.f, dhi = 0.f;
#pragma unroll
    for (int nt = 0; nt < 4; nt++) {
        int col = nt * 8 + (lane & 3) * 2;
        float w0 = a2s[col], w1 = a2s[col + 1];
        float v0 = a2d[col], v1 = a2d[col + 1];
        float c0 = acc[nt][0], c1 = acc[nt][1], c2 = acc[nt][2], c3 = acc[nt][3];
        slo = fmaf(c0, w0, fmaf(c1, w1, slo));
        shi = fmaf(c2, w0, fmaf(c3, w1, shi));
        dlo = fmaf(c0, v0, fmaf(c1, v1, dlo));
        dhi = fmaf(c2, v0, fmaf(c3, v1, dhi));
        if (row_lo < NN) {
            __half2 h = __floats2half2_rn(c0, c1);
            *(__half2*)(n2b + (size_t)row_lo * 72 + 4 + col * 2) = h;
        }
        if (row_hi < NN) {
            __half2 h = __floats2half2_rn(c2, c3);
            *(__half2*)(n2b + (size_t)row_hi * 72 + 4 + col * 2) = h;
        }
    }
    slo += __shfl_xor_sync(0xffffffffu, slo, 1);
    slo += __shfl_xor_sync(0xffffffffu, slo, 2);
    shi += __shfl_xor_sync(0xffffffffu, shi, 1);
    shi += __shfl_xor_sync(0xffffffffu, shi, 2);
    dlo += __shfl_xor_sync(0xffffffffu, dlo, 1);
    dlo += __shfl_xor_sync(0xffffffffu, dlo, 2);
    dhi += __shfl_xor_sync(0xffffffffu, dhi, 1);
    dhi += __shfl_xor_sync(0xffffffffu, dhi, 2);
    if ((lane & 3) == 0) {
        if (row_lo < NN) {
            *(float*)(n2b + (size_t)row_lo * 72) = slo * L2E;
            g_ad2[row_lo] = dlo * L2E;
        }
        if (row_hi < NN) {
            *(float*)(n2b + (size_t)row_hi * 72) = shi * L2E;
            g_ad2[row_hi] = dhi * L2E;
        }
    }
}

// ---------------- Layer-2 fused attention + aggregation + head --------------
// Record offset = csrb >> 2 (72 = 288/4). Predicated final batch, no pad kernel.
__global__ void k_agg2(const float* __restrict__ b2, const float* __restrict__ Wh,
                       const float* __restrict__ bh, float* __restrict__ out) {
    int wid = threadIdx.x >> 5, lane = threadIdx.x & 31;
    int n = blockIdx.x * 8 + wid;
    if (n >= NN) return;
    int beg = n * CAP;
    int deg = g_deg[n];
    int end4 = beg + (deg & ~3);
    int rem = deg & 3;
    int offH = 4 + lane * 2;
    const char* n2b = (const char*)g_n2;

    float ad = g_ad2[n];   // prescaled
    float acc = 0.f, s = 0.f;
    int i = beg;
    for (; i + 8 <= end4; i += 8) {
        unsigned o[8];
#pragma unroll
        for (int j = 0; j < 8; j++) o[j] = __ldg(g_csrb + i + j) >> 2;
        float av[8];
#pragma unroll
        for (int j = 0; j < 8; j++) av[j] = __ldg((const float*)(n2b + o[j]));
        __half hv[8];
#pragma unroll
        for (int j = 0; j < 8; j++) hv[j] = *(const __half*)(n2b + o[j] + offH);
#pragma unroll
        for (int j = 0; j < 8; j++) {
            float w = wexp(av[j] + ad);
            s += w;
            acc = fmaf(w, __half2float(hv[j]), acc);
        }
    }
    if (i < end4) {
        unsigned o[4];
#pragma unroll
        for (int j = 0; j < 4; j++) o[j] = __ldg(g_csrb + i + j) >> 2;
        float av[4];
#pragma unroll
        for (int j = 0; j < 4; j++) av[j] = __ldg((const float*)(n2b + o[j]));
        __half hv[4];
#pragma unroll
        for (int j = 0; j < 4; j++) hv[j] = *(const __half*)(n2b + o[j] + offH);
#pragma unroll
        for (int j = 0; j < 4; j++) {
            float w = wexp(av[j] + ad);
            s += w;
            acc = fmaf(w, __half2float(hv[j]), acc);
        }
        i += 4;
    }
    if (rem) {   // predicated final batch with dummy (w = 0) records
        unsigned o[4];
#pragma unroll
        for (int j = 0; j < 4; j++)
            o[j] = ((j < rem) ? __ldg(g_csrb + i + j) : DUMMY1) >> 2;
        float av[4];
#pragma unroll
        for (int j = 0; j < 4; j++) av[j] = __ldg((const float*)(n2b + o[j]));
        __half hv[4];
#pragma unroll
        for (int j = 0; j < 4; j++) hv[j] = *(const __half*)(n2b + o[j] + offH);
#pragma unroll
        for (int j = 0; j < 4; j++) {
            float w = wexp(av[j] + ad);
            s += w;
            acc = fmaf(w, __half2float(hv[j]), acc);
        }
    }
    float v = eluf(fmaf(acc, 1.f / s, b2[lane]));
    float p = v * Wh[lane];
#pragma unroll
    for (int o = 16; o > 0; o >>= 1) p += __shfl_xor_sync(0xffffffffu, p, o);
    if (lane == 0) out[n] = p + bh[0];
}

// ---------------- launcher ----------------
static cudaStream_t get_side_stream() {
    static cudaStream_t s = [] {
        cudaStream_t t;
        cudaStreamCreateWithFlags(&t, cudaStreamNonBlocking);
        return t;
    }();
    return s;
}
static cudaEvent_t get_event(int which) {
    static cudaEvent_t ev[4] = {};
    static bool done = [] {
        for (int i = 0; i < 4; i++) cudaEventCreateWithFlags(&ev[i], cudaEventDisableTiming);
        return true;
    }();
    (void)done;
    return ev[which];
}

extern "C" void kernel_launch(void* const* d_in, const int* in_sizes, int n_in,
                              void* d_out, int out_size) {
    const float* x   = (const float*)d_in[0];
    const int*   ei  = (const int*)  d_in[1];
    const float* W1  = (const float*)d_in[2];
    const float* a1s = (const float*)d_in[3];
    const float* a1d = (const float*)d_in[4];
    const float* b1  = (const float*)d_in[5];
    const float* W2  = (const float*)d_in[6];
    const float* a2s = (const float*)d_in[7];
    const float* a2d = (const float*)d_in[8];
    const float* b2  = (const float*)d_in[9];
    const float* Wh  = (const float*)d_in[10];
    const float* bh  = (const float*)d_in[11];
    float* out = (float*)d_out;

    cudaStream_t side = get_side_stream();
    cudaEvent_t e_fork = get_event(0);
    cudaEvent_t e_join = get_event(1);
    cudaEvent_t e_a1a  = get_event(2);
    cudaEvent_t e_g2a  = get_event(3);

    // main: init (seeds buckets + dummy record, detects dtype), fork
    k_init<<<(NN + 255) / 256, 256>>>(ei);
    cudaEventRecord(e_fork, 0);
    cudaStreamWaitEvent(side, e_fork, 0);

    // side: bucket fill (hidden under gemm1)
    k_fill<<<(EE + 255) / 256, 256, 0, side>>>(ei);
    cudaEventRecord(e_join, side);

    // main: gemm1 concurrent with fill
    k_gemm1<<<(NN + 127) / 128, 256>>>(x, W1, a1s, a1d);

    // join, then pipelined agg1 halves with gemm2 first half on side stream
    cudaStreamWaitEvent(0, e_join, 0);
    k_agg1<<<HALF_N / 8, 256>>>(b1, 0);
    cudaEventRecord(e_a1a, 0);
    k_agg1<<<(NN - HALF_N + 7) / 8, 256>>>(b1, HALF_N);

    cudaStreamWaitEvent(side, e_a1a, 0);
    k_gemm2<<<HALF_N / 128, 256, 0, side>>>(W2, a2s, a2d, 0);
    cudaEventRecord(e_g2a, side);

    k_gemm2<<<(NN - HALF_N + 127) / 128, 256>>>(W2, a2s, a2d, HALF_N);
    cudaStreamWaitEvent(0, e_g2a, 0);
    k_agg2<<<(NN + 7) / 8, 256>>>(b2, Wh, bh, out);
}

// round 16
// speedup vs baseline: 1.0515x; 1.0515x over previous
#include <cuda_runtime.h>
#include <cuda_fp16.h>

// ---------------- problem constants ----------------
#define NN 100000
#define EE 1600000
#define CAP 64               // bucket capacity per node (max in-degree+1 ~ 43; +3 pad)
#define L2E 1.4426950408889634f
#define HALF_N 50048         // agg1/gemm2 split point (mult of 128 and 8)

// ---------------- device scratch (no allocs allowed) ----------------
__device__ int    g_is64;
__device__ int    g_deg[NN];
__device__ unsigned g_csrb[NN * CAP];    // adjacency: BYTE offsets src*288
// layer-1 node record: 288B = 8 x f32 prescaled-as1 | 128 x f16 h1  (+1 dummy)
__device__ uint4  g_n1[(NN + 1) * 18];
__device__ float  g_ad1[NN * 8];         // prescaled by log2e
__device__ __half g_x2h[NN * 128];       // layer-2 input, fp16
// layer-2 node record: 72B = f32 prescaled-as2 | 32 x f16 h2 | 4B pad (+1 dummy)
__device__ unsigned long long g_n2[(NN + 1) * 9];
__device__ float  g_ad2[NN];             // prescaled by log2e

// ---------------- helpers ----------------
__device__ __forceinline__ float eluf(float x)  { return x > 0.f ? x : __expf(x) - 1.f; }
__device__ __forceinline__ float ex2f(float y) {
    float w;
    asm("ex2.approx.ftz.f32 %0, %1;" : "=f"(w) : "f"(y));
    return w;
}
// exp(lrelu(x/l2e)) where x is prescaled: ex2(max(x, 0.2x))
__device__ __forceinline__ float wexp(float x) {
    return ex2f(fmaxf(x, 0.2f * x));
}

// ---------------- init: seed buckets + dummy record + dtype detection -------
__global__ void k_init(const int* __restrict__ ei) {
    int i = blockIdx.x * blockDim.x + threadIdx.x;
    if (i < NN) {
        g_deg[i] = 1;                     // slot 0 = self loop
        g_csrb[i * CAP] = (unsigned)i * 288u;
    }
    if (blockIdx.x == 0) {
        int t = threadIdx.x;
        if (t < 32) {
            int z = 0;
#pragma unroll
            for (int j = 0; j < 4; j++) z |= ei[2 * (t * 4 + j) + 1];
#pragma unroll
            for (int o = 16; o > 0; o >>= 1) z |= __shfl_xor_sync(0xffffffffu, z, o);
            if (t == 0) g_is64 = (z == 0) ? 1 : 0;
        }
        // dummy node record NN: logits = -1e30 (w = 0), features = 0
        if (t >= 32 && t < 50) {
            int q = t - 32;               // 0..17 -> n1 dummy uint4s
            uint4 v = make_uint4(0, 0, 0, 0);
            if (q < 2) {
                unsigned u = __float_as_uint(-1e30f);
                v = make_uint4(u, u, u, u);
            }
            g_n1[NN * 18 + q] = v;
        }
        if (t >= 50 && t < 59) {
            int q = t - 50;               // 0..8 -> n2 dummy u64s
            g_n2[NN * 9 + q] = (q == 0)
                ? (unsigned long long)__float_as_uint(-1e30f) : 0ull;
        }
    }
}

// ---------------- single-pass bucket fill ----------------
__global__ void k_fill(const int* __restrict__ ei) {
    int e = blockIdx.x * blockDim.x + threadIdx.x;
    if (e >= EE) return;
    int s, d;
    if (g_is64) {
        s = ((const int2*)ei)[e].x;
        d = ((const int2*)ei)[EE + e].x;
    } else {
        s = ei[e];
        d = ei[EE + e];
    }
    int pos = atomicAdd(&g_deg[d], 1);
    g_csrb[d * CAP + pos] = (unsigned)s * 288u;
}

// ---------------- pad buckets to multiple of 4 with dummy (w=0) edges -------
__global__ void k_pad() {
    int i = blockIdx.x * blockDim.x + threadIdx.x;
    if (i >= NN) return;
    int d = g_deg[i];
    int e = (d + 3) & ~3;
    for (int p = d; p < e; p++) g_csrb[i * CAP + p] = (unsigned)NN * 288u;
}

// ---------------- GEMM1 via HMMA: h1 = x @ W1 [128x128] fp16 in, fp32 acc ---
#define APITCH 72    // halfs; 144B rows
#define BPITCH 136   // halfs; 272B rows

__device__ __forceinline__ uint4 pack8(float4 v0, float4 v1) {
    __half2 h0 = __floats2half2_rn(v0.x, v0.y);
    __half2 h1 = __floats2half2_rn(v0.z, v0.w);
    __half2 h2 = __floats2half2_rn(v1.x, v1.y);
    __half2 h3 = __floats2half2_rn(v1.z, v1.w);
    uint4 u;
    u.x = *(unsigned*)&h0; u.y = *(unsigned*)&h1;
    u.z = *(unsigned*)&h2; u.w = *(unsigned*)&h3;
    return u;
}

__global__ void __launch_bounds__(256, 2)
k_gemm1(const float* __restrict__ x, const float* __restrict__ W,
        const float* __restrict__ asv, const float* __restrict__ adv) {
    __shared__ __half As[128 * APITCH];
    __shared__ __half Bs[64 * BPITCH];
    int t = threadIdx.x;
    int lane = t & 31, wid = t >> 5;
    int warp_m = wid >> 1, warp_n = wid & 1;
    int row0 = blockIdx.x * 128;

    float acc[2][8][4];
#pragma unroll
    for (int mt = 0; mt < 2; mt++)
#pragma unroll
        for (int nt = 0; nt < 8; nt++)
#pragma unroll
            for (int q = 0; q < 4; q++) acc[mt][nt][q] = 0.f;

    for (int kc = 0; kc < 2; kc++) {
        __syncthreads();
#pragma unroll
        for (int it = 0; it < 4; it++) {
            int idx = it * 256 + t;
            int r = idx >> 3, c8 = (idx & 7) << 3;
            float4 v0 = make_float4(0.f, 0.f, 0.f, 0.f), v1 = v0;
            if (row0 + r < NN) {
                const float* p = x + (size_t)(row0 + r) * 128 + kc * 64 + c8;
                v0 = *(const float4*)p;
                v1 = *(const float4*)(p + 4);
            }
            *(uint4*)(As + r * APITCH + c8) = pack8(v0, v1);
        }
#pragma unroll
        for (int it = 0; it < 4; it++) {
            int idx = it * 256 + t;
            int k = idx >> 4, nc = (idx & 15) << 3;
            const float* p = W + (size_t)(kc * 64 + k) * 128 + nc;
            float4 v0 = *(const float4*)p;
            float4 v1 = *(const float4*)(p + 4);
            *(uint4*)(Bs + k * BPITCH + nc) = pack8(v0, v1);
        }
        __syncthreads();

#pragma unroll
        for (int ks = 0; ks < 4; ks++) {
            unsigned af[2][4], bf[4][4];
#pragma unroll
            for (int mt = 0; mt < 2; mt++) {
                int r = warp_m * 32 + mt * 16 + (lane & 15);
                int k = ks * 16 + ((lane >> 4) << 3);
                unsigned ad = (unsigned)__cvta_generic_to_shared(As + r * APITCH + k);
                asm volatile("ldmatrix.sync.aligned.m8n8.x4.shared.b16 {%0,%1,%2,%3}, [%4];"
                             : "=r"(af[mt][0]), "=r"(af[mt][1]), "=r"(af[mt][2]), "=r"(af[mt][3])
                             : "r"(ad));
            }
#pragma unroll
            for (int np = 0; np < 4; np++) {
                int k = ks * 16 + (lane & 15);
                int n = warp_n * 64 + np * 16 + ((lane >> 4) << 3);
                unsigned ad = (unsigned)__cvta_generic_to_shared(Bs + k * BPITCH + n);
                asm volatile("ldmatrix.sync.aligned.m8n8.x4.trans.shared.b16 {%0,%1,%2,%3}, [%4];"
                             : "=r"(bf[np][0]), "=r"(bf[np][1]), "=r"(bf[np][2]), "=r"(bf[np][3])
                             : "r"(ad));
            }
#pragma unroll
            for (int mt = 0; mt < 2; mt++)
#pragma unroll
                for (int nt = 0; nt < 8; nt++) {
                    unsigned b0 = bf[nt >> 1][(nt & 1) * 2];
                    unsigned b1 = bf[nt >> 1][(nt & 1) * 2 + 1];
                    asm volatile(
                        "mma.sync.aligned.m16n8k16.row.col.f32.f16.f16.f32 "
                        "{%0,%1,%2,%3}, {%4,%5,%6,%7}, {%8,%9}, {%0,%1,%2,%3};"
                        : "+f"(acc[mt][nt][0]), "+f"(acc[mt][nt][1]),
                          "+f"(acc[mt][nt][2]), "+f"(acc[mt][nt][3])
                        : "r"(af[mt][0]), "r"(af[mt][1]), "r"(af[mt][2]), "r"(af[mt][3]),
                          "r"(b0), "r"(b1));
                }
        }
    }

    float aw0[8], aw1[8], dw0[8], dw1[8];
#pragma unroll
    for (int nt = 0; nt < 8; nt++) {
        int col = warp_n * 64 + nt * 8 + (lane & 3) * 2;
        aw0[nt] = asv[col];     aw1[nt] = asv[col + 1];
        dw0[nt] = adv[col];     dw1[nt] = adv[col + 1];
    }
    char* n1b = (char*)g_n1;
#pragma unroll
    for (int mt = 0; mt < 2; mt++) {
        int row_lo = row0 + warp_m * 32 + mt * 16 + (lane >> 2);
        int row_hi = row_lo + 8;
        float slo[4] = {0,0,0,0}, shi[4] = {0,0,0,0};
        float dlo[4] = {0,0,0,0}, dhi[4] = {0,0,0,0};
#pragma unroll
        for (int nt = 0; nt < 8; nt++) {
            float c0 = acc[mt][nt][0], c1 = acc[mt][nt][1];
            float c2 = acc[mt][nt][2], c3 = acc[mt][nt][3];
            int col = warp_n * 64 + nt * 8 + (lane & 3) * 2;
            if (row_lo < NN) {
                __half2 h = __floats2half2_rn(c0, c1);
                *(__half2*)(n1b + (size_t)row_lo * 288 + 32 + col * 2) = h;
            }
            if (row_hi < NN) {
                __half2 h = __floats2half2_rn(c2, c3);
                *(__half2*)(n1b + (size_t)row_hi * 288 + 32 + col * 2) = h;
            }
            int hl = nt >> 1;
            slo[hl] = fmaf(c0, aw0[nt], fmaf(c1, aw1[nt], slo[hl]));
            shi[hl] = fmaf(c2, aw0[nt], fmaf(c3, aw1[nt], shi[hl]));
            dlo[hl] = fmaf(c0, dw0[nt], fmaf(c1, dw1[nt], dlo[hl]));
            dhi[hl] = fmaf(c2, dw0[nt], fmaf(c3, dw1[nt], dhi[hl]));
        }
#pragma unroll
        for (int hl = 0; hl < 4; hl++) {
            slo[hl] += __shfl_xor_sync(0xffffffffu, slo[hl], 1);
            slo[hl] += __shfl_xor_sync(0xffffffffu, slo[hl], 2);
            shi[hl] += __shfl_xor_sync(0xffffffffu, shi[hl], 1);
            shi[hl] += __shfl_xor_sync(0xffffffffu, shi[hl], 2);
            dlo[hl] += __shfl_xor_sync(0xffffffffu, dlo[hl], 1);
            dlo[hl] += __shfl_xor_sync(0xffffffffu, dlo[hl], 2);
            dhi[hl] += __shfl_xor_sync(0xffffffffu, dhi[hl], 1);
            dhi[hl] += __shfl_xor_sync(0xffffffffu, dhi[hl], 2);
        }
        if ((lane & 3) == 0) {
            int hbase = warp_n * 4;
#pragma unroll
            for (int hl = 0; hl < 4; hl++) {
                int h = hbase + hl;
                if (row_lo < NN) {
                    *(float*)(n1b + (size_t)row_lo * 288 + h * 4) = slo[hl] * L2E;
                    g_ad1[row_lo * 8 + h] = dlo[hl] * L2E;
                }
                if (row_hi < NN) {
                    *(float*)(n1b + (size_t)row_hi * 288 + h * 4) = shi[hl] * L2E;
                    g_ad1[row_hi * 8 + h] = dhi[hl] * L2E;
                }
            }
        }
    }
}

// ---------------- Layer-1 fused attention + aggregation ----------------
// Round-11 form (independent per-lane loads, batch 8 then 4); buckets are
// padded to a multiple of 4 with zero-weight dummy edges, so no tail loop.
__global__ void k_agg1(const float* __restrict__ b1, int n0) {
    int wid = threadIdx.x >> 5, lane = threadIdx.x & 31;
    int n = n0 + blockIdx.x * 8 + wid;
    if (n >= NN) return;
    int beg = n * CAP;
    int end = beg + ((g_deg[n] + 3) & ~3);
    int offA = (lane >> 2) * 4;
    int offH = 32 + lane * 8;
    const char* n1b = (const char*)g_n1;

    float ad = g_ad1[n * 8 + (lane >> 2)];   // prescaled by log2e

    float4 acc = make_float4(0.f, 0.f, 0.f, 0.f);
    float s = 0.f;
    int i = beg;
    for (; i + 8 <= end; i += 8) {
        unsigned o[8];
#pragma unroll
        for (int j = 0; j < 8; j++) o[j] = __ldg(g_csrb + i + j);
        float av[8];
#pragma unroll
        for (int j = 0; j < 8; j++) av[j] = __ldg((const float*)(n1b + o[j] + offA));
        uint2 uv[8];
#pragma unroll
        for (int j = 0; j < 8; j++) uv[j] = __ldg((const uint2*)(n1b + o[j] + offH));
#pragma unroll
        for (int j = 0; j < 8; j++) {
            float w = wexp(av[j] + ad);
            s += w;
            float2 f0 = __half22float2(*(__half2*)&uv[j].x);
            float2 f1 = __half22float2(*(__half2*)&uv[j].y);
            acc.x = fmaf(w, f0.x, acc.x); acc.y = fmaf(w, f0.y, acc.y);
            acc.z = fmaf(w, f1.x, acc.z); acc.w = fmaf(w, f1.y, acc.w);
        }
    }
    if (i < end) {   // exactly one 4-batch remains (padding guarantees)
        unsigned o[4];
#pragma unroll
        for (int j = 0; j < 4; j++) o[j] = __ldg(g_csrb + i + j);
        float av[4];
#pragma unroll
        for (int j = 0; j < 4; j++) av[j] = __ldg((const float*)(n1b + o[j] + offA));
        uint2 uv[4];
#pragma unroll
        for (int j = 0; j < 4; j++) uv[j] = __ldg((const uint2*)(n1b + o[j] + offH));
#pragma unroll
        for (int j = 0; j < 4; j++) {
            float w = wexp(av[j] + ad);
            s += w;
            float2 f0 = __half22float2(*(__half2*)&uv[j].x);
            float2 f1 = __half22float2(*(__half2*)&uv[j].y);
            acc.x = fmaf(w, f0.x, acc.x); acc.y = fmaf(w, f0.y, acc.y);
            acc.z = fmaf(w, f1.x, acc.z); acc.w = fmaf(w, f1.y, acc.w);
        }
    }
    float rv = 1.f / s;   // s >= w(selfloop) > 0
    float4 bb = *(const float4*)(b1 + lane * 4);
    __half2 o0 = __floats2half2_rn(eluf(fmaf(acc.x, rv, bb.x)), eluf(fmaf(acc.y, rv, bb.y)));
    __half2 o1 = __floats2half2_rn(eluf(fmaf(acc.z, rv, bb.z)), eluf(fmaf(acc.w, rv, bb.w)));
    uint2 ov;
    ov.x = *(unsigned*)&o0;
    ov.y = *(unsigned*)&o1;
    *(uint2*)(g_x2h + (size_t)n * 128 + lane * 4) = ov;
}

// ---------------- GEMM2 via HMMA: h2 = x2h @ W2 [128x32] fp16 in, fp32 acc --
#define A2PITCH 136   // halfs; 272B rows
#define B2PITCH 40    // halfs; 80B rows
__global__ void __launch_bounds__(256, 2)
k_gemm2(const float* __restrict__ W, const float* __restrict__ a2s,
        const float* __restrict__ a2d, int r0) {
    __shared__ __half As[128 * A2PITCH];
    __shared__ __half Bs[128 * B2PITCH];
    int t = threadIdx.x;
    int lane = t & 31, wid = t >> 5;
    int row0 = r0 + blockIdx.x * 128;

#pragma unroll
    for (int it = 0; it < 8; it++) {
        int idx = it * 256 + t;
        int r = idx >> 4, c = (idx & 15) << 3;
        uint4 v = make_uint4(0, 0, 0, 0);
        if (row0 + r < NN) v = *(const uint4*)(g_x2h + (size_t)(row0 + r) * 128 + c);
        *(uint4*)(As + r * A2PITCH + c) = v;
    }
#pragma unroll
    for (int it = 0; it < 8; it++) {
        int idx = it * 256 + t;
        int k = idx >> 4, n2 = (idx & 15) << 1;
        float2 w = *(const float2*)(W + k * 32 + n2);
        *(__half2*)(Bs + k * B2PITCH + n2) = __floats2half2_rn(w.x, w.y);
    }
    __syncthreads();

    float acc[4][4];
#pragma unroll
    for (int nt = 0; nt < 4; nt++)
#pragma unroll
        for (int q = 0; q < 4; q++) acc[nt][q] = 0.f;

#pragma unroll
    for (int ks = 0; ks < 8; ks++) {
        unsigned af[4], bf[2][4];
        {
            int r = wid * 16 + (lane & 15);
            int k = ks * 16 + ((lane >> 4) << 3);
            unsigned ad = (unsigned)__cvta_generic_to_shared(As + r * A2PITCH + k);
            asm volatile("ldmatrix.sync.aligned.m8n8.x4.shared.b16 {%0,%1,%2,%3}, [%4];"
                         : "=r"(af[0]), "=r"(af[1]), "=r"(af[2]), "=r"(af[3]) : "r"(ad));
        }
#pragma unroll
        for (int np = 0; np < 2; np++) {
            int k = ks * 16 + (lane & 15);
            int n = np * 16 + ((lane >> 4) << 3);
            unsigned ad = (unsigned)__cvta_generic_to_shared(Bs + k * B2PITCH + n);
            asm volatile("ldmatrix.sync.aligned.m8n8.x4.trans.shared.b16 {%0,%1,%2,%3}, [%4];"
                         : "=r"(bf[np][0]), "=r"(bf[np][1]), "=r"(bf[np][2]), "=r"(bf[np][3])
                         : "r"(ad));
        }
#pragma unroll
        for (int nt = 0; nt < 4; nt++) {
            unsigned b0 = bf[nt >> 1][(nt & 1) * 2];
            unsigned b1 = bf[nt >> 1][(nt & 1) * 2 + 1];
            asm volatile(
                "mma.sync.aligned.m16n8k16.row.col.f32.f16.f16.f32 "
                "{%0,%1,%2,%3}, {%4,%5,%6,%7}, {%8,%9}, {%0,%1,%2,%3};"
                : "+f"(acc[nt][0]), "+f"(acc[nt][1]), "+f"(acc[nt][2]), "+f"(acc[nt][3])
                : "r"(af[0]), "r"(af[1]), "r"(af[2]), "r"(af[3]), "r"(b0), "r"(b1));
        }
    }

    char* n2b = (char*)g_n2;
    int row_lo = row0 + wid * 16 + (lane >> 2);
    int row_hi = row_lo + 8;
    float slo = 0.f, shi = 0.f, dlo = 0.f, dhi = 0.f;
#pragma unroll
    for (int nt = 0; nt < 4; nt++) {
        int col = nt * 8 + (lane & 3) * 2;
        float w0 = a2s[col], w1 = a2s[col + 1];
        float v0 = a2d[col], v1 = a2d[col + 1];
        float c0 = acc[nt][0], c1 = acc[nt][1], c2 = acc[nt][2], c3 = acc[nt][3];
        slo = fmaf(c0, w0, fmaf(c1, w1, slo));
        shi = fmaf(c2, w0, fmaf(c3, w1, shi));
        dlo = fmaf(c0, v0, fmaf(c1, v1, dlo));
        dhi = fmaf(c2, v0, fmaf(c3, v1, dhi));
        if (row_lo < NN) {
            __half2 h = __floats2half2_rn(c0, c1);
            *(__half2*)(n2b + (size_t)row_lo * 72 + 4 + col * 2) = h;
        }
        if (row_hi < NN) {
            __half2 h = __floats2half2_rn(c2, c3);
            *(__half2*)(n2b + (size_t)row_hi * 72 + 4 + col * 2) = h;
        }
    }
    slo += __shfl_xor_sync(0xffffffffu, slo, 1);
    slo += __shfl_xor_sync(0xffffffffu, slo, 2);
    shi += __shfl_xor_sync(0xffffffffu, shi, 1);
    shi += __shfl_xor_sync(0xffffffffu, shi, 2);
    dlo += __shfl_xor_sync(0xffffffffu, dlo, 1);
    dlo += __shfl_xor_sync(0xffffffffu, dlo, 2);
    dhi += __shfl_xor_sync(0xffffffffu, dhi, 1);
    dhi += __shfl_xor_sync(0xffffffffu, dhi, 2);
    if ((lane & 3) == 0) {
        if (row_lo < NN) {
            *(float*)(n2b + (size_t)row_lo * 72) = slo * L2E;
            g_ad2[row_lo] = dlo * L2E;
        }
        if (row_hi < NN) {
            *(float*)(n2b + (size_t)row_hi * 72) = shi * L2E;
            g_ad2[row_hi] = dhi * L2E;
        }
    }
}

// ---------------- Layer-2 fused attention + aggregation + head --------------
// Round-11 form; padded buckets => no tail loop. Record offset = csrb >> 2.
__global__ void k_agg2(const float* __restrict__ b2, const float* __restrict__ Wh,
                       const float* __restrict__ bh, float* __restrict__ out) {
    int wid = threadIdx.x >> 5, lane = threadIdx.x & 31;
    int n = blockIdx.x * 8 + wid;
    if (n >= NN) return;
    int beg = n * CAP;
    int end = beg + ((g_deg[n] + 3) & ~3);
    int offH = 4 + lane * 2;
    const char* n2b = (const char*)g_n2;

    float ad = g_ad2[n];   // prescaled
    float acc = 0.f, s = 0.f;
    int i = beg;
    for (; i + 8 <= end; i += 8) {
        unsigned o[8];
#pragma unroll
        for (int j = 0; j < 8; j++) o[j] = __ldg(g_csrb + i + j) >> 2;
        float av[8];
#pragma unroll
        for (int j = 0; j < 8; j++) av[j] = __ldg((const float*)(n2b + o[j]));
        __half hv[8];
#pragma unroll
        for (int j = 0; j < 8; j++) hv[j] = *(const __half*)(n2b + o[j] + offH);
#pragma unroll
        for (int j = 0; j < 8; j++) {
            float w = wexp(av[j] + ad);
            s += w;
            acc = fmaf(w, __half2float(hv[j]), acc);
        }
    }
    if (i < end) {   // exactly one 4-batch remains
        unsigned o[4];
#pragma unroll
        for (int j = 0; j < 4; j++) o[j] = __ldg(g_csrb + i + j) >> 2;
        float av[4];
#pragma unroll
        for (int j = 0; j < 4; j++) av[j] = __ldg((const float*)(n2b + o[j]));
        __half hv[4];
#pragma unroll
        for (int j = 0; j < 4; j++) hv[j] = *(const __half*)(n2b + o[j] + offH);
#pragma unroll
        for (int j = 0; j < 4; j++) {
            float w = wexp(av[j] + ad);
            s += w;
            acc = fmaf(w, __half2float(hv[j]), acc);
        }
    }
    float v = eluf(fmaf(acc, 1.f / s, b2[lane]));
    float p = v * Wh[lane];
#pragma unroll
    for (int o = 16; o > 0; o >>= 1) p += __shfl_xor_sync(0xffffffffu, p, o);
    if (lane == 0) out[n] = p + bh[0];
}

// ---------------- launcher ----------------
static cudaStream_t get_side_stream() {
    static cudaStream_t s = [] {
        cudaStream_t t;
        cudaStreamCreateWithFlags(&t, cudaStreamNonBlocking);
        return t;
    }();
    return s;
}
static cudaEvent_t get_event(int which) {
    static cudaEvent_t ev[4] = {};
    static bool done = [] {
        for (int i = 0; i < 4; i++) cudaEventCreateWithFlags(&ev[i], cudaEventDisableTiming);
        return true;
    }();
    (void)done;
    return ev[which];
}

extern "C" void kernel_launch(void* const* d_in, const int* in_sizes, int n_in,
                              void* d_out, int out_size) {
    const float* x   = (const float*)d_in[0];
    const int*   ei  = (const int*)  d_in[1];
    const float* W1  = (const float*)d_in[2];
    const float* a1s = (const float*)d_in[3];
    const float* a1d = (const float*)d_in[4];
    const float* b1  = (const float*)d_in[5];
    const float* W2  = (const float*)d_in[6];
    const float* a2s = (const float*)d_in[7];
    const float* a2d = (const float*)d_in[8];
    const float* b2  = (const float*)d_in[9];
    const float* Wh  = (const float*)d_in[10];
    const float* bh  = (const float*)d_in[11];
    float* out = (float*)d_out;

    cudaStream_t side = get_side_stream();
    cudaEvent_t e_fork = get_event(0);
    cudaEvent_t e_join = get_event(1);
    cudaEvent_t e_a1a  = get_event(2);
    cudaEvent_t e_g2a  = get_event(3);

    // main: init (seeds buckets + dummy record, detects dtype), fork
    k_init<<<(NN + 255) / 256, 256>>>(ei);
    cudaEventRecord(e_fork, 0);
    cudaStreamWaitEvent(side, e_fork, 0);

    // side: bucket fill + pad-to-4 (hidden under gemm1)
    k_fill<<<(EE + 255) / 256, 256, 0, side>>>(ei);
    k_pad<<<(NN + 255) / 256, 256, 0, side>>>();
    cudaEventRecord(e_join, side);

    // main: gemm1 concurrent with fill+pad
    k_gemm1<<<(NN + 127) / 128, 256>>>(x, W1, a1s, a1d);

    // join, then pipelined agg1 halves with gemm2 first half on side stream
    cudaStreamWaitEvent(0, e_join, 0);
    k_agg1<<<HALF_N / 8, 256>>>(b1, 0);
    cudaEventRecord(e_a1a, 0);
    k_agg1<<<(NN - HALF_N + 7) / 8, 256>>>(b1, HALF_N);

    cudaStreamWaitEvent(side, e_a1a, 0);
    k_gemm2<<<HALF_N / 128, 256, 0, side>>>(W2, a2s, a2d, 0);
    cudaEventRecord(e_g2a, side);

    k_gemm2<<<(NN - HALF_N + 127) / 128, 256>>>(W2, a2s, a2d, HALF_N);
    cudaStreamWaitEvent(0, e_g2a, 0);
    k_agg2<<<(NN + 7) / 8, 256>>>(b2, Wh, bh, out);
}